// round 2
// baseline (speedup 1.0000x reference)
#include <cuda_runtime.h>
#include <math.h>

#define BN 4
#define IH 512
#define IW 512
#define TT 32            // TV output tile
#define RMAX 44          // TT + 2*6

// ---------------- static scratch ----------------
__device__ float g_pA[BN*2*IH*IW];
__device__ float g_pB[BN*2*IH*IW];
__device__ float g_den[BN*IH*IW];
__device__ float g_bufA[8*1024*1024];     // 32MB
__device__ float g_bufB[4*1024*1024];     // 16MB
__device__ float g_weff[1281];
__device__ float g_s[BN*256];

__device__ __forceinline__ float silu(float x){ return x/(1.f+__expf(-x)); }

// ---------------- TV Chambolle: 5 fused iterations, in-place p in smem ----------------
template<int HALO, bool FIRST, bool WRITE_P, bool WRITE_DEN>
__global__ __launch_bounds__(256)
void tv_fused_k(const float* __restrict__ img, const float* __restrict__ pin,
                float* __restrict__ pout, float* __restrict__ den){
    const int R = TT + 2*HALO;
    __shared__ float si[RMAX*RMAX], s0[RMAX*RMAX], s1[RMAX*RMAX], so[RMAX*RMAX];
    const int b   = blockIdx.z;
    const int gy0 = blockIdx.y*TT - HALO;
    const int gx0 = blockIdx.x*TT - HALO;
    const float* ib = img + b*IH*IW;
    const float* q0 = pin + (b*2+0)*IH*IW;
    const float* q1 = pin + (b*2+1)*IH*IW;
    const int tid = threadIdx.x;

    // load img (+ p) region; invariant: p slots outside image hold 0
    for(int i=tid;i<R*R;i+=256){
        int ly=i/R, lx=i-ly*R;
        int gy=gy0+ly, gx=gx0+lx;
        bool in = (gy>=0 && gy<IH && gx>=0 && gx<IW);
        int g = gy*IW+gx;
        si[i] = in ? ib[g] : 0.f;
        if(FIRST){ s0[i]=0.f; s1[i]=0.f; }
        else { s0[i] = in ? q0[g] : 0.f; s1[i] = in ? q1[g] : 0.f; }
    }
    __syncthreads();

#pragma unroll 1
    for(int it=0; it<5; it++){
        // out = img + div(p). valid on ly>=1,lx>=1 (garbage ring consumed by halo)
        for(int i=tid;i<R*R;i+=256){
            int ly=i/R, lx=i-ly*R;
            float v=0.f;
            if(ly>=1 && lx>=1)
                v = si[i] - s0[i] - s1[i] + s0[i-R] + s1[i-1];
            so[i]=v;
        }
        __syncthreads();
        // p <- (p - tau*grad(out)) / (1 + (tau/w)|grad|)   (in-place: reads p only at i)
        for(int i=tid;i<R*R;i+=256){
            int ly=i/R, lx=i-ly*R;
            if(ly>=R-1 || lx>=R-1) continue;
            int gy=gy0+ly, gx=gx0+lx;
            float o   = so[i];
            float gyv = (gy<IH-1) ? so[i+R]-o : 0.f;
            float gxv = (gx<IW-1) ? so[i+1]-o : 0.f;
            float nrm = sqrtf(gyv*gyv + gxv*gxv);
            float inv = 1.f/(1.f + 2.5f*nrm);
            bool in = (gy>=0 && gy<IH && gx>=0 && gx<IW);
            s0[i] = in ? (s0[i] - 0.25f*gyv)*inv : 0.f;
            s1[i] = in ? (s1[i] - 0.25f*gxv)*inv : 0.f;
        }
        __syncthreads();
    }

    if(WRITE_P){
        float* o0 = pout + (b*2+0)*IH*IW;
        float* o1 = pout + (b*2+1)*IH*IW;
        for(int i=tid;i<TT*TT;i+=256){
            int ty=i>>5, tx=i&31;
            int s=(ty+HALO)*R + tx+HALO;
            int g=(gy0+ty+HALO)*IW + gx0+tx+HALO;
            o0[g]=s0[s]; o1[g]=s1[s];
        }
    }
    if(WRITE_DEN){
        float* db = den + b*IH*IW;
        for(int i=tid;i<TT*TT;i+=256){
            int ty=i>>5, tx=i&31;
            int s=(ty+HALO)*R + tx+HALO;
            db[(gy0+ty+HALO)*IW + gx0+tx+HALO] = si[s] - s0[s] - s1[s] + s0[s-R] + s1[s-1];
        }
    }
}

// ---------------- fused stem(3x3 s2, 1->32) + dw1(3x3 s2 depthwise) + silu ----------------
// block: 16x16 dw1-output tile, all 32 channels (4-channel groups). grid (8,8,BN)
__global__ __launch_bounds__(256)
void stemdw_k(const float* __restrict__ x, const float* __restrict__ sw_g,
              const float* __restrict__ dw_g, float* __restrict__ y){
    __shared__ float sin_[67*67];       // input patch
    __shared__ float sst[4*33*33];      // stem outputs for 4 channels
    __shared__ float wst[288], wdw[288];
    const int b  = blockIdx.z;
    const int t0y= blockIdx.y*16, t0x = blockIdx.x*16;   // dw1 out origin
    const int tid= threadIdx.x;
    for(int i=tid;i<288;i+=256){ wst[i]=sw_g[i]; wdw[i]=dw_g[i]; }
    // input region origin: (4*t0y-3, 4*t0x-3), 67x67
    const float* xb = x + b*IH*IW;
    for(int i=tid;i<67*67;i+=256){
        int ly=i/67, lx=i-ly*67;
        int gy=4*t0y-3+ly, gx=4*t0x-3+lx;
        sin_[i] = (gy>=0&&gy<IH&&gx>=0&&gx<IW) ? xb[gy*IW+gx] : 0.f;
    }
    __syncthreads();

    for(int cg=0; cg<8; cg++){
        // stem: 33x33 region, stem-out origin (2*t0y-1, 2*t0x-1), channels cg*4..cg*4+3
        for(int i=tid;i<33*33*4;i+=256){
            int c  = i/1089;
            int r  = i-c*1089;
            int sy = r/33, sx = r-sy*33;
            int gsy= 2*t0y-1+sy, gsx = 2*t0x-1+sx;
            float v = 0.f;
            if(gsy>=0 && gsy<256 && gsx>=0 && gsx<256){
                const float* wc = wst + (cg*4+c)*9;
                int base = (2*sy)*67 + 2*sx;   // input local: liy=2*sy+ky, lix=2*sx+kx
                float acc = 0.f;
#pragma unroll
                for(int ky=0;ky<3;ky++)
#pragma unroll
                for(int kx=0;kx<3;kx++)
                    acc += sin_[base+ky*67+kx]*wc[ky*3+kx];
                v = silu(acc);
            }
            sst[c*1089 + r] = v;
        }
        __syncthreads();
        // dw1: 16x16 per channel, stem local idx: sy = 2*oy+ky, sx = 2*ox+kx (oy local)
        for(int i=tid;i<16*16*4;i+=256){
            int c  = i>>8;
            int r  = i&255;
            int oy = r>>4, ox = r&15;
            const float* wc = wdw + (cg*4+c)*9;
            const float* sc = sst + c*1089;
            float acc=0.f;
#pragma unroll
            for(int ky=0;ky<3;ky++)
#pragma unroll
            for(int kx=0;kx<3;kx++)
                acc += sc[(2*oy+ky)*33 + 2*ox+kx]*wc[ky*3+kx];
            y[(size_t)((b*32 + cg*4+c)*128 + t0y+oy)*128 + t0x+ox] = silu(acc);
        }
        __syncthreads();
    }
}

// ---------------- depthwise 3x3 stride2 + silu ----------------
__global__ void dw_k(const float* __restrict__ x, const float* __restrict__ w,
                     float* __restrict__ y, int C, int Hi, int Ho){
    int idx = blockIdx.x*256 + threadIdx.x;
    if(idx >= BN*C*Ho*Ho) return;
    int ox = idx % Ho; int t = idx/Ho; int oy=t%Ho; t/=Ho; int c=t%C; int b=t/C;
    const float* xb = x + (size_t)(b*C+c)*Hi*Hi;
    const float* wc = w + c*9;
    float acc=0.f;
#pragma unroll
    for(int ky=0;ky<3;ky++){
        int iy=2*oy-1+ky; if(iy<0||iy>=Hi) continue;
#pragma unroll
        for(int kx=0;kx<3;kx++){
            int ix=2*ox-1+kx; if(ix<0||ix>=Hi) continue;
            acc += xb[iy*Hi+ix]*wc[ky*3+kx];
        }
    }
    y[idx] = silu(acc);
}

// ---------------- pointwise 1x1 + silu: GEMM M(Co) x N(pix) x K(Ci) ----------------
__global__ void pw_k(const float* __restrict__ x, const float* __restrict__ w,
                     float* __restrict__ y, int M, int K, int HW){
    int b = blockIdx.z, m0 = blockIdx.y*64, p0 = blockIdx.x*64;
    __shared__ float As[16][64];
    __shared__ float Bs[16][64];
    int tid = threadIdx.x;
    int tr = tid>>4, tc = tid&15;
    float acc[4][4] = {};
    const float* xb = x + (size_t)b*K*HW;
    for(int k0=0;k0<K;k0+=16){
#pragma unroll
        for(int r=0;r<4;r++){
            int id = tid + 256*r;
            int m  = id>>4, kk = id&15;
            As[kk][m] = w[(m0+m)*K + k0 + kk];
            int kk2 = id>>6, p = id&63;
            Bs[kk2][p] = xb[(size_t)(k0+kk2)*HW + p0 + p];
        }
        __syncthreads();
#pragma unroll
        for(int kk=0;kk<16;kk++){
            float a0=As[kk][tr*4+0], a1=As[kk][tr*4+1], a2=As[kk][tr*4+2], a3=As[kk][tr*4+3];
            float b0=Bs[kk][tc*4+0], b1=Bs[kk][tc*4+1], b2=Bs[kk][tc*4+2], b3=Bs[kk][tc*4+3];
            acc[0][0]+=a0*b0; acc[0][1]+=a0*b1; acc[0][2]+=a0*b2; acc[0][3]+=a0*b3;
            acc[1][0]+=a1*b0; acc[1][1]+=a1*b1; acc[1][2]+=a1*b2; acc[1][3]+=a1*b3;
            acc[2][0]+=a2*b0; acc[2][1]+=a2*b1; acc[2][2]+=a2*b2; acc[2][3]+=a2*b3;
            acc[3][0]+=a3*b0; acc[3][1]+=a3*b1; acc[3][2]+=a3*b2; acc[3][3]+=a3*b3;
        }
        __syncthreads();
    }
#pragma unroll
    for(int i=0;i<4;i++)
#pragma unroll
    for(int j=0;j<4;j++)
        y[(size_t)(b*M + m0 + tr*4+i)*HW + p0 + tc*4+j] = silu(acc[i][j]);
}

// ---------------- fold final_w . proj_w ----------------
__global__ void weff_k(const float* __restrict__ proj_w, const float* __restrict__ proj_b,
                       const float* __restrict__ final_w, float* __restrict__ out){
    int k = blockIdx.x*256 + threadIdx.x;
    if(k < 1280){
        float acc=0.f;
        for(int c=0;c<64;c++) acc += final_w[c]*proj_w[c*1280 + k];
        out[k]=acc;
    }
    if(k == 1280){
        float acc=0.f;
        for(int c=0;c<64;c++) acc += final_w[c]*proj_b[c];
        out[1280]=acc;
    }
}

// ---------------- s[b,p] = sum_k w_eff[k]*head[b,k,p] + beta ----------------
__global__ void s_k(const float* __restrict__ head, const float* __restrict__ weff,
                    float* __restrict__ s){
    __shared__ float sw[1280];
    int b = blockIdx.x, tid = threadIdx.x;
    for(int i=tid;i<1280;i+=256) sw[i]=weff[i];
    __syncthreads();
    const float* hb = head + (size_t)b*1280*256 + tid;
    float acc = weff[1280];
    for(int k=0;k<1280;k++) acc += sw[k]*hb[(size_t)k*256];
    s[b*256+tid] = acc;
}

// ---------------- out = 0.25*sum_{4x4} clamped-bilinear(s) + final_b ----------------
__global__ void final_k(const float* __restrict__ s, const float* __restrict__ final_b,
                        float* __restrict__ out){
    int b = blockIdx.x >> 6;
    __shared__ float ss[256];
    int tid = threadIdx.x;
    ss[tid] = s[b*256 + tid];
    __syncthreads();
    int idx = blockIdx.x*256 + tid;
    int r = idx & 16383; int i = r>>7, j = r&127;
    float acc = 0.f;
#pragma unroll
    for(int dy=0;dy<4;dy++){
        float fy  = (4*i+dy+0.5f)*(1.f/32.f) - 0.5f;
        float y0f = floorf(fy); float f = fy - y0f;
        int y0 = (int)y0f;
        int iy0 = min(max(y0,0),15), iy1 = min(max(y0+1,0),15);
#pragma unroll
        for(int dx=0;dx<4;dx++){
            float fx  = (4*j+dx+0.5f)*(1.f/32.f) - 0.5f;
            float x0f = floorf(fx); float g = fx - x0f;
            int x0 = (int)x0f;
            int ix0 = min(max(x0,0),15), ix1 = min(max(x0+1,0),15);
            float top = ss[iy0*16+ix0]*(1.f-g) + ss[iy0*16+ix1]*g;
            float bot = ss[iy1*16+ix0]*(1.f-g) + ss[iy1*16+ix1]*g;
            acc += top*(1.f-f) + bot*f;
        }
    }
    out[idx] = 0.25f*acc + final_b[0];
}

// ---------------- launch ----------------
extern "C" void kernel_launch(void* const* d_in, const int* in_sizes, int n_in,
                              void* d_out, int out_size){
    const float* img     = (const float*)d_in[0];
    const float* stem_w  = (const float*)d_in[1];
    const float* dw1_w   = (const float*)d_in[2];
    const float* pw1_w   = (const float*)d_in[3];
    const float* dw2_w   = (const float*)d_in[4];
    const float* pw2_w   = (const float*)d_in[5];
    const float* dw3_w   = (const float*)d_in[6];
    const float* pw3_w   = (const float*)d_in[7];
    const float* dw4_w   = (const float*)d_in[8];
    const float* pw4_w   = (const float*)d_in[9];
    const float* head_w  = (const float*)d_in[10];
    const float* proj_w  = (const float*)d_in[11];
    const float* proj_b  = (const float*)d_in[12];
    const float* final_w = (const float*)d_in[13];
    const float* final_b = (const float*)d_in[14];

    float *pA,*pB,*den,*bA,*bB,*weff,*sbuf;
    cudaGetSymbolAddress((void**)&pA,  g_pA);
    cudaGetSymbolAddress((void**)&pB,  g_pB);
    cudaGetSymbolAddress((void**)&den, g_den);
    cudaGetSymbolAddress((void**)&bA,  g_bufA);
    cudaGetSymbolAddress((void**)&bB,  g_bufB);
    cudaGetSymbolAddress((void**)&weff,g_weff);
    cudaGetSymbolAddress((void**)&sbuf,g_s);

    // TV: 20 iterations in 4 fused launches (5 each); last also emits denoised img
    dim3 tvg(IW/TT, IH/TT, BN);
    tv_fused_k<5,true ,true ,false><<<tvg,256>>>(img, pA, pA, den);   // iters 1-5  -> pA
    tv_fused_k<5,false,true ,false><<<tvg,256>>>(img, pA, pB, den);   // iters 6-10 -> pB
    tv_fused_k<5,false,true ,false><<<tvg,256>>>(img, pB, pA, den);   // iters 11-15-> pA
    tv_fused_k<6,false,false,true ><<<tvg,256>>>(img, pA, pB, den);   // iters 16-20-> den

    // fused stem + dw1 -> [4,32,128,128] in bB
    stemdw_k<<<dim3(8,8,BN),256>>>(den, stem_w, dw1_w, bB);

    pw_k<<<dim3(16384/64, 64/64,  BN),256>>>(bB, pw1_w, bA, 64,  32, 16384);
    dw_k<<<(BN*64*64*64)/256,256>>>(bA, dw2_w, bB, 64, 128, 64);
    pw_k<<<dim3(4096/64, 128/64,  BN),256>>>(bB, pw2_w, bA, 128, 64, 4096);
    dw_k<<<(BN*128*32*32)/256,256>>>(bA, dw3_w, bB, 128, 64, 32);
    pw_k<<<dim3(1024/64, 256/64,  BN),256>>>(bB, pw3_w, bA, 256, 128, 1024);
    dw_k<<<(BN*256*16*16)/256,256>>>(bA, dw4_w, bB, 256, 32, 16);
    pw_k<<<dim3(256/64,  512/64,  BN),256>>>(bB, pw4_w, bA, 512, 256, 256);
    pw_k<<<dim3(256/64, 1280/64,  BN),256>>>(bA, head_w, bB, 1280, 512, 256);

    weff_k<<<6,256>>>(proj_w, proj_b, final_w, weff);
    s_k<<<BN,256>>>(bB, weff, sbuf);
    final_k<<<BN*64,256>>>(sbuf, final_b, (float*)d_out);
}

// round 3
// speedup vs baseline: 1.0653x; 1.0653x over previous
#include <cuda_runtime.h>
#include <math.h>

#define BN 4
#define IH 512
#define IW 512
// TV tiling: R=64 region, TT=52 output tile, HALO=6, 5 iters per launch
#define TT 52
#define HALO 6
#define PADL 64
#define ASZ (4096+128)
#define TV_SMEM (3*ASZ*4)

// ---------------- static scratch ----------------
__device__ float g_pA[BN*2*IH*IW];
__device__ float g_pB[BN*2*IH*IW];
__device__ float g_den[BN*IH*IW];
__device__ float g_bufA[8*1024*1024];     // 32MB
__device__ float g_bufB[4*1024*1024];     // 16MB
__device__ float g_weff[1281];
__device__ float g_s[BN*256];

__device__ __forceinline__ float silu(float x){ return x/(1.f+__expf(-x)); }

// ---------------- TV Chambolle: 5 fused iterations, register p, shift indexing ----------------
template<bool FIRST, bool INTERIOR, bool WRITE_P, bool WRITE_DEN>
__device__ __forceinline__ void tv_body(
    const float* __restrict__ img, const float* __restrict__ pin,
    float* __restrict__ pout, float* __restrict__ den,
    float* s0, float* s1, float* so)
{
    const int b   = blockIdx.z;
    const int gy0 = blockIdx.y*TT - HALO;
    const int gx0 = blockIdx.x*TT - HALO;
    const int tid = threadIdx.x;
    const int lx  = tid & 63;
    const int ty0 = tid >> 6;            // ly = ty0 + 4k
    const int gx  = gx0 + lx;
    const float* ib = img + b*(IH*IW);
    const float* q0 = pin + (b*2+0)*(IH*IW);
    const float* q1 = pin + (b*2+1)*(IH*IW);

    float sir[16], p0r[16], p1r[16];
    const bool inx = ((unsigned)gx < IW);
    const bool mx  = (gx < IW-1);

#pragma unroll
    for(int k=0;k<16;k++){
        const int ly = ty0 + 4*k;
        const int gy = gy0 + ly;
        const int i  = k*256 + tid;
        const int g  = gy*IW + gx;
        if(INTERIOR){
            sir[k] = ib[g];
            if(FIRST){ p0r[k]=0.f; p1r[k]=0.f; }
            else     { p0r[k]=q0[g]; p1r[k]=q1[g]; }
        } else {
            const bool in = ((unsigned)gy < IH) && inx;
            sir[k] = in ? ib[g] : 0.f;
            if(FIRST){ p0r[k]=0.f; p1r[k]=0.f; }
            else     { p0r[k]= in? q0[g]:0.f; p1r[k]= in? q1[g]:0.f; }
        }
        s0[i]=p0r[k]; s1[i]=p1r[k];
    }
    __syncthreads();

#pragma unroll 1
    for(int it=0; it<5; it++){
        // pass 1: out = img + div(p). row0/col0 garbage is consumed by halo shrink.
#pragma unroll
        for(int k=0;k<16;k++){
            const int i = k*256 + tid;
            so[i] = sir[k] - p0r[k] - p1r[k] + s0[i-64] + s1[i-1];
        }
        __syncthreads();
        // pass 2: p <- (p - tau*grad(out)) / (1 + (tau/w)|grad|)
#pragma unroll
        for(int k=0;k<16;k++){
            const int i  = k*256 + tid;
            const int gy = gy0 + ty0 + 4*k;
            const float o = so[i];
            float gyv = so[i+64] - o;
            float gxv = so[i+1]  - o;
            if(!INTERIOR){
                if(gy >= IH-1) gyv = 0.f;
                if(!mx)        gxv = 0.f;
            }
            const float n2 = fmaf(gyv,gyv, gxv*gxv);
            float nr;  asm("sqrt.approx.f32 %0, %1;" : "=f"(nr)  : "f"(n2));
            const float dn = fmaf(2.5f, nr, 1.0f);
            float inv; asm("rcp.approx.f32 %0, %1;"  : "=f"(inv) : "f"(dn));
            float np0 = (p0r[k] - 0.25f*gyv)*inv;
            float np1 = (p1r[k] - 0.25f*gxv)*inv;
            if(!INTERIOR){
                const bool in = ((unsigned)gy < IH) && inx;
                if(!in){ np0=0.f; np1=0.f; }
            }
            p0r[k]=np0; p1r[k]=np1;
            s0[i]=np0;  s1[i]=np1;
        }
        __syncthreads();
    }

    const bool wx = (lx>=HALO) && (lx<HALO+TT) && (gx<IW);
    if(WRITE_P){
        float* o0 = pout + (b*2+0)*(IH*IW);
        float* o1 = pout + (b*2+1)*(IH*IW);
#pragma unroll
        for(int k=0;k<16;k++){
            const int ly = ty0+4*k, gy = gy0+ly;
            if(wx && ly>=HALO && ly<HALO+TT && gy<IH){
                o0[gy*IW+gx]=p0r[k]; o1[gy*IW+gx]=p1r[k];
            }
        }
    }
    if(WRITE_DEN){
#pragma unroll
        for(int k=0;k<16;k++){
            const int ly = ty0+4*k, gy = gy0+ly;
            const int i  = k*256+tid;
            if(wx && ly>=HALO && ly<HALO+TT && gy<IH){
                den[b*(IH*IW)+gy*IW+gx] = sir[k]-p0r[k]-p1r[k]+s0[i-64]+s1[i-1];
            }
        }
    }
}

template<bool FIRST, bool WRITE_P, bool WRITE_DEN>
__global__ __launch_bounds__(256,3)
void tv5_k(const float* __restrict__ img, const float* __restrict__ pin,
           float* __restrict__ pout, float* __restrict__ den){
    extern __shared__ float sm[];
    float* s0 = sm + PADL;
    float* s1 = sm + ASZ   + PADL;
    float* so = sm + 2*ASZ + PADL;
    const bool interior = (blockIdx.y>=1 && blockIdx.y<=8 &&
                           blockIdx.x>=1 && blockIdx.x<=8);
    if(interior) tv_body<FIRST,true ,WRITE_P,WRITE_DEN>(img,pin,pout,den,s0,s1,so);
    else         tv_body<FIRST,false,WRITE_P,WRITE_DEN>(img,pin,pout,den,s0,s1,so);
}

// ---------------- stem: 1->32ch 3x3 stride2 + silu ----------------
__global__ void stem_k(const float* __restrict__ x, const float* __restrict__ w,
                       float* __restrict__ y){
    __shared__ float sw[288];
    for(int i=threadIdx.x;i<288;i+=256) sw[i]=w[i];
    __syncthreads();
    int idx = blockIdx.x*256 + threadIdx.x;
    int b = idx>>16; int r = idx & 65535; int oy=r>>8, ox=r&255;
    const float* xb = x + b*IH*IW;
    float patch[9];
#pragma unroll
    for(int ky=0;ky<3;ky++)
#pragma unroll
    for(int kx=0;kx<3;kx++){
        int iy=2*oy-1+ky, ix=2*ox-1+kx;
        patch[ky*3+kx] = (iy>=0&&iy<IH&&ix>=0&&ix<IW)? xb[iy*IW+ix] : 0.f;
    }
    float* yb = y + (size_t)(b*32)*65536 + oy*256 + ox;
#pragma unroll
    for(int c=0;c<32;c++){
        float acc=0.f;
#pragma unroll
        for(int k=0;k<9;k++) acc += patch[k]*sw[c*9+k];
        yb[c*65536] = silu(acc);
    }
}

// ---------------- depthwise 3x3 stride2 + silu ----------------
__global__ void dw_k(const float* __restrict__ x, const float* __restrict__ w,
                     float* __restrict__ y, int C, int Hi, int Ho){
    int idx = blockIdx.x*256 + threadIdx.x;
    if(idx >= BN*C*Ho*Ho) return;
    int ox = idx % Ho; int t = idx/Ho; int oy=t%Ho; t/=Ho; int c=t%C; int b=t/C;
    const float* xb = x + (size_t)(b*C+c)*Hi*Hi;
    const float* wc = w + c*9;
    float acc=0.f;
#pragma unroll
    for(int ky=0;ky<3;ky++){
        int iy=2*oy-1+ky; if(iy<0||iy>=Hi) continue;
#pragma unroll
        for(int kx=0;kx<3;kx++){
            int ix=2*ox-1+kx; if(ix<0||ix>=Hi) continue;
            acc += xb[iy*Hi+ix]*wc[ky*3+kx];
        }
    }
    y[idx] = silu(acc);
}

// ---------------- pointwise 1x1 + silu ----------------
__global__ void pw_k(const float* __restrict__ x, const float* __restrict__ w,
                     float* __restrict__ y, int M, int K, int HW){
    int b = blockIdx.z, m0 = blockIdx.y*64, p0 = blockIdx.x*64;
    __shared__ float As[16][64];
    __shared__ float Bs[16][64];
    int tid = threadIdx.x;
    int tr = tid>>4, tc = tid&15;
    float acc[4][4] = {};
    const float* xb = x + (size_t)b*K*HW;
    for(int k0=0;k0<K;k0+=16){
#pragma unroll
        for(int r=0;r<4;r++){
            int id = tid + 256*r;
            int m  = id>>4, kk = id&15;
            As[kk][m] = w[(m0+m)*K + k0 + kk];
            int kk2 = id>>6, p = id&63;
            Bs[kk2][p] = xb[(size_t)(k0+kk2)*HW + p0 + p];
        }
        __syncthreads();
#pragma unroll
        for(int kk=0;kk<16;kk++){
            float a0=As[kk][tr*4+0], a1=As[kk][tr*4+1], a2=As[kk][tr*4+2], a3=As[kk][tr*4+3];
            float b0=Bs[kk][tc*4+0], b1=Bs[kk][tc*4+1], b2=Bs[kk][tc*4+2], b3=Bs[kk][tc*4+3];
            acc[0][0]+=a0*b0; acc[0][1]+=a0*b1; acc[0][2]+=a0*b2; acc[0][3]+=a0*b3;
            acc[1][0]+=a1*b0; acc[1][1]+=a1*b1; acc[1][2]+=a1*b2; acc[1][3]+=a1*b3;
            acc[2][0]+=a2*b0; acc[2][1]+=a2*b1; acc[2][2]+=a2*b2; acc[2][3]+=a2*b3;
            acc[3][0]+=a3*b0; acc[3][1]+=a3*b1; acc[3][2]+=a3*b2; acc[3][3]+=a3*b3;
        }
        __syncthreads();
    }
#pragma unroll
    for(int i=0;i<4;i++)
#pragma unroll
    for(int j=0;j<4;j++)
        y[(size_t)(b*M + m0 + tr*4+i)*HW + p0 + tc*4+j] = silu(acc[i][j]);
}

// ---------------- fold final_w . proj_w ----------------
__global__ void weff_k(const float* __restrict__ proj_w, const float* __restrict__ proj_b,
                       const float* __restrict__ final_w, float* __restrict__ out){
    int k = blockIdx.x*256 + threadIdx.x;
    if(k < 1280){
        float acc=0.f;
        for(int c=0;c<64;c++) acc += final_w[c]*proj_w[c*1280 + k];
        out[k]=acc;
    }
    if(k == 1280){
        float acc=0.f;
        for(int c=0;c<64;c++) acc += final_w[c]*proj_b[c];
        out[1280]=acc;
    }
}

// ---------------- s[b,p] = sum_k w_eff[k]*head[b,k,p] + beta  (split-K + atomicAdd) ----------------
__global__ void s_part_k(const float* __restrict__ head, const float* __restrict__ weff,
                         float* __restrict__ s){
    const int b = blockIdx.y, chunk = blockIdx.x;   // 8 chunks of 160 k's
    __shared__ float sw[160];
    const int tid = threadIdx.x;
    if(tid < 160) sw[tid] = weff[chunk*160 + tid];
    __syncthreads();
    const float* hb = head + ((size_t)b*1280 + chunk*160)*256 + tid;
    float acc = (chunk==0) ? weff[1280] : 0.f;
#pragma unroll 4
    for(int k=0;k<160;k++) acc += sw[k]*hb[(size_t)k*256];
    atomicAdd(&s[b*256 + tid], acc);
}

// ---------------- out = 0.25*sum_{4x4} clamped-bilinear(s) + final_b ----------------
__global__ void final_k(const float* __restrict__ s, const float* __restrict__ final_b,
                        float* __restrict__ out){
    int b = blockIdx.x >> 6;
    __shared__ float ss[256];
    int tid = threadIdx.x;
    ss[tid] = s[b*256 + tid];
    __syncthreads();
    int idx = blockIdx.x*256 + tid;
    int r = idx & 16383; int i = r>>7, j = r&127;
    float acc = 0.f;
#pragma unroll
    for(int dy=0;dy<4;dy++){
        float fy  = (4*i+dy+0.5f)*(1.f/32.f) - 0.5f;
        float y0f = floorf(fy); float f = fy - y0f;
        int y0 = (int)y0f;
        int iy0 = min(max(y0,0),15), iy1 = min(max(y0+1,0),15);
#pragma unroll
        for(int dx=0;dx<4;dx++){
            float fx  = (4*j+dx+0.5f)*(1.f/32.f) - 0.5f;
            float x0f = floorf(fx); float g = fx - x0f;
            int x0 = (int)x0f;
            int ix0 = min(max(x0,0),15), ix1 = min(max(x0+1,0),15);
            float top = ss[iy0*16+ix0]*(1.f-g) + ss[iy0*16+ix1]*g;
            float bot = ss[iy1*16+ix0]*(1.f-g) + ss[iy1*16+ix1]*g;
            acc += top*(1.f-f) + bot*f;
        }
    }
    out[idx] = 0.25f*acc + final_b[0];
}

// ---------------- launch ----------------
extern "C" void kernel_launch(void* const* d_in, const int* in_sizes, int n_in,
                              void* d_out, int out_size){
    const float* img     = (const float*)d_in[0];
    const float* stem_w  = (const float*)d_in[1];
    const float* dw1_w   = (const float*)d_in[2];
    const float* pw1_w   = (const float*)d_in[3];
    const float* dw2_w   = (const float*)d_in[4];
    const float* pw2_w   = (const float*)d_in[5];
    const float* dw3_w   = (const float*)d_in[6];
    const float* pw3_w   = (const float*)d_in[7];
    const float* dw4_w   = (const float*)d_in[8];
    const float* pw4_w   = (const float*)d_in[9];
    const float* head_w  = (const float*)d_in[10];
    const float* proj_w  = (const float*)d_in[11];
    const float* proj_b  = (const float*)d_in[12];
    const float* final_w = (const float*)d_in[13];
    const float* final_b = (const float*)d_in[14];

    float *pA,*pB,*den,*bA,*bB,*weff,*sbuf;
    cudaGetSymbolAddress((void**)&pA,  g_pA);
    cudaGetSymbolAddress((void**)&pB,  g_pB);
    cudaGetSymbolAddress((void**)&den, g_den);
    cudaGetSymbolAddress((void**)&bA,  g_bufA);
    cudaGetSymbolAddress((void**)&bB,  g_bufB);
    cudaGetSymbolAddress((void**)&weff,g_weff);
    cudaGetSymbolAddress((void**)&sbuf,g_s);

    cudaFuncSetAttribute(tv5_k<true ,true ,false>, cudaFuncAttributeMaxDynamicSharedMemorySize, TV_SMEM);
    cudaFuncSetAttribute(tv5_k<false,true ,false>, cudaFuncAttributeMaxDynamicSharedMemorySize, TV_SMEM);
    cudaFuncSetAttribute(tv5_k<false,false,true >, cudaFuncAttributeMaxDynamicSharedMemorySize, TV_SMEM);

    // TV: 20 iterations in 4 launches of 5; last also emits denoised image
    dim3 tvg(10,10,BN);
    tv5_k<true ,true ,false><<<tvg,256,TV_SMEM>>>(img, pA, pA, den);  // 1-5   -> pA
    tv5_k<false,true ,false><<<tvg,256,TV_SMEM>>>(img, pA, pB, den);  // 6-10  -> pB
    tv5_k<false,true ,false><<<tvg,256,TV_SMEM>>>(img, pB, pA, den);  // 11-15 -> pA
    tv5_k<false,false,true ><<<tvg,256,TV_SMEM>>>(img, pA, pB, den);  // 16-20 -> den

    // backbone
    stem_k<<<(BN*256*256)/256,256>>>(den, stem_w, bA);                  // [4,32,256,256]
    dw_k<<<(BN*32*128*128)/256,256>>>(bA, dw1_w, bB, 32, 256, 128);     // [4,32,128,128]
    pw_k<<<dim3(16384/64, 64/64,  BN),256>>>(bB, pw1_w, bA, 64,  32, 16384);
    dw_k<<<(BN*64*64*64)/256,256>>>(bA, dw2_w, bB, 64, 128, 64);
    pw_k<<<dim3(4096/64, 128/64,  BN),256>>>(bB, pw2_w, bA, 128, 64, 4096);
    dw_k<<<(BN*128*32*32)/256,256>>>(bA, dw3_w, bB, 128, 64, 32);
    pw_k<<<dim3(1024/64, 256/64,  BN),256>>>(bB, pw3_w, bA, 256, 128, 1024);
    dw_k<<<(BN*256*16*16)/256,256>>>(bA, dw4_w, bB, 256, 32, 16);
    pw_k<<<dim3(256/64,  512/64,  BN),256>>>(bB, pw4_w, bA, 512, 256, 256);
    pw_k<<<dim3(256/64, 1280/64,  BN),256>>>(bA, head_w, bB, 1280, 512, 256);

    // folded tail
    weff_k<<<6,256>>>(proj_w, proj_b, final_w, weff);
    cudaMemsetAsync(sbuf, 0, BN*256*sizeof(float));
    s_part_k<<<dim3(8,BN),256>>>(bB, weff, sbuf);
    final_k<<<BN*64,256>>>(sbuf, final_b, (float*)d_out);
}

// round 4
// speedup vs baseline: 1.5990x; 1.5010x over previous
#include <cuda_runtime.h>
#include <math.h>

#define BN 4
#define IH 512
#define IW 512
// TV tiling: R=64 (32 float2), TT=52, HALO=6, 5 iters per launch
#define TT 52
#define HALO 6
#define PAD2 32
#define A2 2112                   // float2 slots per array: 32 pad + 2048 + 32 pad
#define TV_SMEM (3*A2*8)

// ---------------- static scratch ----------------
__device__ float g_pA[BN*2*IH*IW];
__device__ float g_pB[BN*2*IH*IW];
__device__ float g_den[BN*IH*IW];
__device__ float g_bufA[8*1024*1024];
__device__ float g_bufB[4*1024*1024];
__device__ float g_weff[1281];
__device__ float g_s[BN*256];

__device__ __forceinline__ float silu(float x){ return x/(1.f+__expf(-x)); }

// ---------------- TV Chambolle: 5 fused iterations, float2 vectorized ----------------
template<bool FIRST, bool INTERIOR, bool WRITE_P, bool WRITE_DEN>
__device__ __forceinline__ void tv_body(
    const float* __restrict__ img, const float* __restrict__ pin,
    float* __restrict__ pout, float* __restrict__ den,
    float2* s0, float2* s1, float2* so)
{
    const int b   = blockIdx.z;
    const int gy0 = blockIdx.y*TT - HALO;
    const int gx0 = blockIdx.x*TT - HALO;
    const int tid = threadIdx.x;
    const int lx2 = tid & 31;          // float2 column
    const int ty0 = tid >> 5;          // row base; ly = ty0 + 8k
    const int gxp = gx0 + 2*lx2;       // global col of .x (even)
    const float* ib = img + b*(IH*IW);
    const float* q0 = pin + (b*2+0)*(IH*IW);
    const float* q1 = pin + (b*2+1)*(IH*IW);

    float2 imgv[8], p0v[8], p1v[8];

#pragma unroll
    for(int k=0;k<8;k++){
        const int ly = ty0 + 8*k;
        const int gy = gy0 + ly;
        const int i  = k*256 + tid;
        if(INTERIOR){
            const int g2 = gy*(IW/2) + (gxp>>1);
            imgv[k] = ((const float2*)ib)[g2];
            if(FIRST){ p0v[k]=make_float2(0.f,0.f); p1v[k]=make_float2(0.f,0.f); }
            else { p0v[k]=((const float2*)q0)[g2]; p1v[k]=((const float2*)q1)[g2]; }
        } else {
            const bool iy  = ((unsigned)gy < IH);
            const bool inx = iy && ((unsigned)gxp < IW);
            const bool iny = iy && ((unsigned)(gxp+1) < IW);
            const int gA = gy*IW + gxp, gB = gA+1;
            imgv[k].x = inx ? ib[gA] : 0.f;
            imgv[k].y = iny ? ib[gB] : 0.f;
            if(FIRST){ p0v[k]=make_float2(0.f,0.f); p1v[k]=make_float2(0.f,0.f); }
            else{
                p0v[k].x = inx? q0[gA]:0.f; p0v[k].y = iny? q0[gB]:0.f;
                p1v[k].x = inx? q1[gA]:0.f; p1v[k].y = iny? q1[gB]:0.f;
            }
        }
        s0[i]=p0v[k]; s1[i]=p1v[k];
    }
    __syncthreads();

#pragma unroll 1
    for(int it=0; it<5; it++){
        // pass1: out = img + div(p)
#pragma unroll
        for(int k=0;k<8;k++){
            const int i = k*256 + tid;
            float2 up = s0[i-32];
            float  lf = s1[i-1].y;
            float2 o;
            o.x = imgv[k].x - p0v[k].x - p1v[k].x + up.x + lf;
            o.y = imgv[k].y - p0v[k].y - p1v[k].y + up.y + p1v[k].x;
            so[i] = o;
        }
        __syncthreads();
        // pass2: p update
#pragma unroll
        for(int k=0;k<8;k++){
            const int i  = k*256 + tid;
            const int gy = gy0 + ty0 + 8*k;
            float2 o  = so[i];
            float2 dn = so[i+32];
            float  rx = so[i+1].x;
            float gyx = dn.x - o.x, gyy = dn.y - o.y;
            float gxx = o.y  - o.x, gxy = rx   - o.y;
            if(!INTERIOR){
                if(gy >= IH-1){ gyx=0.f; gyy=0.f; }
                if(gxp+1 >= IW-1) gxy = 0.f;
            }
            float n2x = fmaf(gyx,gyx, gxx*gxx);
            float n2y = fmaf(gyy,gyy, gxy*gxy);
            float nrx, nry, ivx, ivy;
            asm("sqrt.approx.f32 %0, %1;" : "=f"(nrx) : "f"(n2x));
            asm("sqrt.approx.f32 %0, %1;" : "=f"(nry) : "f"(n2y));
            float dx_ = fmaf(2.5f, nrx, 1.0f);
            float dy_ = fmaf(2.5f, nry, 1.0f);
            asm("rcp.approx.f32 %0, %1;" : "=f"(ivx) : "f"(dx_));
            asm("rcp.approx.f32 %0, %1;" : "=f"(ivy) : "f"(dy_));
            float2 np0, np1;
            np0.x = (p0v[k].x - 0.25f*gyx)*ivx;
            np1.x = (p1v[k].x - 0.25f*gxx)*ivx;
            np0.y = (p0v[k].y - 0.25f*gyy)*ivy;
            np1.y = (p1v[k].y - 0.25f*gxy)*ivy;
            if(!INTERIOR){
                const bool iy  = ((unsigned)gy < IH);
                const bool inx = iy && ((unsigned)gxp < IW);
                const bool iny = iy && ((unsigned)(gxp+1) < IW);
                if(!inx){ np0.x=0.f; np1.x=0.f; }
                if(!iny){ np0.y=0.f; np1.y=0.f; }
            }
            p0v[k]=np0; p1v[k]=np1;
            s0[i]=np0;  s1[i]=np1;
        }
        __syncthreads();
    }

    const bool wx = (lx2>=3) && (lx2<29) && (gxp < IW);
    if(WRITE_P){
        float2* o0 = (float2*)(pout + (b*2+0)*(IH*IW));
        float2* o1 = (float2*)(pout + (b*2+1)*(IH*IW));
#pragma unroll
        for(int k=0;k<8;k++){
            const int ly = ty0+8*k, gy = gy0+ly;
            if(wx && ly>=HALO && ly<HALO+TT && gy<IH){
                const int g2 = gy*(IW/2) + (gxp>>1);
                o0[g2]=p0v[k]; o1[g2]=p1v[k];
            }
        }
    }
    if(WRITE_DEN){
        float2* db = (float2*)(den + b*(IH*IW));
#pragma unroll
        for(int k=0;k<8;k++){
            const int ly = ty0+8*k, gy = gy0+ly;
            const int i  = k*256+tid;
            if(wx && ly>=HALO && ly<HALO+TT && gy<IH){
                float2 up = s0[i-32];
                float  lf = s1[i-1].y;
                float2 d;
                d.x = imgv[k].x - p0v[k].x - p1v[k].x + up.x + lf;
                d.y = imgv[k].y - p0v[k].y - p1v[k].y + up.y + p1v[k].x;
                db[gy*(IW/2) + (gxp>>1)] = d;
            }
        }
    }
}

template<bool FIRST, bool WRITE_P, bool WRITE_DEN>
__global__ __launch_bounds__(256,3)
void tv5_k(const float* __restrict__ img, const float* __restrict__ pin,
           float* __restrict__ pout, float* __restrict__ den){
    extern __shared__ float2 sm2[];
    float2* s0 = sm2 + PAD2;
    float2* s1 = sm2 + A2   + PAD2;
    float2* so = sm2 + 2*A2 + PAD2;
    const bool interior = (blockIdx.y>=1 && blockIdx.y<=8 &&
                           blockIdx.x>=1 && blockIdx.x<=8);
    if(interior) tv_body<FIRST,true ,WRITE_P,WRITE_DEN>(img,pin,pout,den,s0,s1,so);
    else         tv_body<FIRST,false,WRITE_P,WRITE_DEN>(img,pin,pout,den,s0,s1,so);
}

// ---------------- stem: 1->32ch 3x3 stride2 + silu ----------------
__global__ void stem_k(const float* __restrict__ x, const float* __restrict__ w,
                       float* __restrict__ y){
    __shared__ float sw[288];
    for(int i=threadIdx.x;i<288;i+=256) sw[i]=w[i];
    __syncthreads();
    int idx = blockIdx.x*256 + threadIdx.x;
    int b = idx>>16; int r = idx & 65535; int oy=r>>8, ox=r&255;
    const float* xb = x + b*IH*IW;
    float patch[9];
#pragma unroll
    for(int ky=0;ky<3;ky++)
#pragma unroll
    for(int kx=0;kx<3;kx++){
        int iy=2*oy-1+ky, ix=2*ox-1+kx;
        patch[ky*3+kx] = (iy>=0&&iy<IH&&ix>=0&&ix<IW)? xb[iy*IW+ix] : 0.f;
    }
    float* yb = y + (size_t)(b*32)*65536 + oy*256 + ox;
#pragma unroll
    for(int c=0;c<32;c++){
        float acc=0.f;
#pragma unroll
        for(int k=0;k<9;k++) acc += patch[k]*sw[c*9+k];
        yb[c*65536] = silu(acc);
    }
}

// ---------------- depthwise 3x3 stride2 + silu ----------------
__global__ void dw_k(const float* __restrict__ x, const float* __restrict__ w,
                     float* __restrict__ y, int C, int Hi, int Ho){
    int idx = blockIdx.x*256 + threadIdx.x;
    if(idx >= BN*C*Ho*Ho) return;
    int ox = idx % Ho; int t = idx/Ho; int oy=t%Ho; t/=Ho; int c=t%C; int b=t/C;
    const float* xb = x + (size_t)(b*C+c)*Hi*Hi;
    const float* wc = w + c*9;
    float acc=0.f;
#pragma unroll
    for(int ky=0;ky<3;ky++){
        int iy=2*oy-1+ky; if(iy<0||iy>=Hi) continue;
#pragma unroll
        for(int kx=0;kx<3;kx++){
            int ix=2*ox-1+kx; if(ix<0||ix>=Hi) continue;
            acc += xb[iy*Hi+ix]*wc[ky*3+kx];
        }
    }
    y[idx] = silu(acc);
}

// ---------------- big pointwise GEMM: BM=64, BN=128, 128 thr, 8x8 micro ----------------
__global__ __launch_bounds__(128)
void pwb_k(const float* __restrict__ x, const float* __restrict__ w,
           float* __restrict__ y, int M, int K, int HW){
    const int b = blockIdx.z, m0 = blockIdx.y*64, p0 = blockIdx.x*128;
    __shared__ float As[16][68];
    __shared__ float Bs[16][128];
    const int tid = threadIdx.x;
    const int tr = tid>>4, tc = tid&15;
    float acc[8][8] = {};
    const float* xb = x + (size_t)b*K*HW;
    for(int k0=0;k0<K;k0+=16){
#pragma unroll
        for(int r=0;r<2;r++){
            int m = (tid>>2) + 32*r;
            int q = (tid&3)*4;
            float4 v = *(const float4*)&w[(size_t)(m0+m)*K + k0 + q];
            As[q+0][m]=v.x; As[q+1][m]=v.y; As[q+2][m]=v.z; As[q+3][m]=v.w;
        }
#pragma unroll
        for(int r=0;r<4;r++){
            int kk = (tid>>5) + 4*r;
            int p  = (tid&31)*4;
            *(float4*)&Bs[kk][p] = *(const float4*)&xb[(size_t)(k0+kk)*HW + p0 + p];
        }
        __syncthreads();
#pragma unroll
        for(int kk=0;kk<16;kk++){
            float a[8], bv[8];
            *(float4*)&a[0]  = *(float4*)&As[kk][tr*8];
            *(float4*)&a[4]  = *(float4*)&As[kk][tr*8+4];
            *(float4*)&bv[0] = *(float4*)&Bs[kk][tc*8];
            *(float4*)&bv[4] = *(float4*)&Bs[kk][tc*8+4];
#pragma unroll
            for(int i=0;i<8;i++)
#pragma unroll
            for(int j=0;j<8;j++)
                acc[i][j] = fmaf(a[i], bv[j], acc[i][j]);
        }
        __syncthreads();
    }
#pragma unroll
    for(int i=0;i<8;i++){
        float4 o1, o2;
        o1.x=silu(acc[i][0]); o1.y=silu(acc[i][1]); o1.z=silu(acc[i][2]); o1.w=silu(acc[i][3]);
        o2.x=silu(acc[i][4]); o2.y=silu(acc[i][5]); o2.z=silu(acc[i][6]); o2.w=silu(acc[i][7]);
        float* yr = y + (size_t)(b*M + m0 + tr*8 + i)*HW + p0 + tc*8;
        *(float4*)yr     = o1;
        *(float4*)(yr+4) = o2;
    }
}

// ---------------- small pointwise 1x1 + silu (64x64) ----------------
__global__ void pw_k(const float* __restrict__ x, const float* __restrict__ w,
                     float* __restrict__ y, int M, int K, int HW){
    int b = blockIdx.z, m0 = blockIdx.y*64, p0 = blockIdx.x*64;
    __shared__ float As[16][64];
    __shared__ float Bs[16][64];
    int tid = threadIdx.x;
    int tr = tid>>4, tc = tid&15;
    float acc[4][4] = {};
    const float* xb = x + (size_t)b*K*HW;
    for(int k0=0;k0<K;k0+=16){
#pragma unroll
        for(int r=0;r<4;r++){
            int id = tid + 256*r;
            int m  = id>>4, kk = id&15;
            As[kk][m] = w[(m0+m)*K + k0 + kk];
            int kk2 = id>>6, p = id&63;
            Bs[kk2][p] = xb[(size_t)(k0+kk2)*HW + p0 + p];
        }
        __syncthreads();
#pragma unroll
        for(int kk=0;kk<16;kk++){
            float a0=As[kk][tr*4+0], a1=As[kk][tr*4+1], a2=As[kk][tr*4+2], a3=As[kk][tr*4+3];
            float b0=Bs[kk][tc*4+0], b1=Bs[kk][tc*4+1], b2=Bs[kk][tc*4+2], b3=Bs[kk][tc*4+3];
            acc[0][0]+=a0*b0; acc[0][1]+=a0*b1; acc[0][2]+=a0*b2; acc[0][3]+=a0*b3;
            acc[1][0]+=a1*b0; acc[1][1]+=a1*b1; acc[1][2]+=a1*b2; acc[1][3]+=a1*b3;
            acc[2][0]+=a2*b0; acc[2][1]+=a2*b1; acc[2][2]+=a2*b2; acc[2][3]+=a2*b3;
            acc[3][0]+=a3*b0; acc[3][1]+=a3*b1; acc[3][2]+=a3*b2; acc[3][3]+=a3*b3;
        }
        __syncthreads();
    }
#pragma unroll
    for(int i=0;i<4;i++)
#pragma unroll
    for(int j=0;j<4;j++)
        y[(size_t)(b*M + m0 + tr*4+i)*HW + p0 + tc*4+j] = silu(acc[i][j]);
}

// ---------------- fold final_w . proj_w (+ zero s) ----------------
__global__ void weff_k(const float* __restrict__ proj_w, const float* __restrict__ proj_b,
                       const float* __restrict__ final_w, float* __restrict__ out,
                       float* __restrict__ s){
    if(blockIdx.x >= 6){
        int j = (blockIdx.x-6)*256 + threadIdx.x;
        if(j < BN*256) s[j] = 0.f;
        return;
    }
    int k = blockIdx.x*256 + threadIdx.x;
    if(k < 1280){
        float acc=0.f;
        for(int c=0;c<64;c++) acc += final_w[c]*proj_w[c*1280 + k];
        out[k]=acc;
    }
    if(k == 1280){
        float acc=0.f;
        for(int c=0;c<64;c++) acc += final_w[c]*proj_b[c];
        out[1280]=acc;
    }
}

// ---------------- s[b,p] = sum_k w_eff[k]*head[b,k,p] + beta (split-K) ----------------
__global__ void s_part_k(const float* __restrict__ head, const float* __restrict__ weff,
                         float* __restrict__ s){
    const int b = blockIdx.y, chunk = blockIdx.x;
    __shared__ float sw[160];
    const int tid = threadIdx.x;
    if(tid < 160) sw[tid] = weff[chunk*160 + tid];
    __syncthreads();
    const float* hb = head + ((size_t)b*1280 + chunk*160)*256 + tid;
    float acc = (chunk==0) ? weff[1280] : 0.f;
#pragma unroll 4
    for(int k=0;k<160;k++) acc += sw[k]*hb[(size_t)k*256];
    atomicAdd(&s[b*256 + tid], acc);
}

// ---------------- out = 0.25*sum_{4x4} clamped-bilinear(s) + final_b ----------------
__global__ void final_k(const float* __restrict__ s, const float* __restrict__ final_b,
                        float* __restrict__ out){
    int b = blockIdx.x >> 6;
    __shared__ float ss[256];
    int tid = threadIdx.x;
    ss[tid] = s[b*256 + tid];
    __syncthreads();
    int idx = blockIdx.x*256 + tid;
    int r = idx & 16383; int i = r>>7, j = r&127;
    float acc = 0.f;
#pragma unroll
    for(int dy=0;dy<4;dy++){
        float fy  = (4*i+dy+0.5f)*(1.f/32.f) - 0.5f;
        float y0f = floorf(fy); float f = fy - y0f;
        int y0 = (int)y0f;
        int iy0 = min(max(y0,0),15), iy1 = min(max(y0+1,0),15);
#pragma unroll
        for(int dx=0;dx<4;dx++){
            float fx  = (4*j+dx+0.5f)*(1.f/32.f) - 0.5f;
            float x0f = floorf(fx); float g = fx - x0f;
            int x0 = (int)x0f;
            int ix0 = min(max(x0,0),15), ix1 = min(max(x0+1,0),15);
            float top = ss[iy0*16+ix0]*(1.f-g) + ss[iy0*16+ix1]*g;
            float bot = ss[iy1*16+ix0]*(1.f-g) + ss[iy1*16+ix1]*g;
            acc += top*(1.f-f) + bot*f;
        }
    }
    out[idx] = 0.25f*acc + final_b[0];
}

// ---------------- launch ----------------
extern "C" void kernel_launch(void* const* d_in, const int* in_sizes, int n_in,
                              void* d_out, int out_size){
    const float* img     = (const float*)d_in[0];
    const float* stem_w  = (const float*)d_in[1];
    const float* dw1_w   = (const float*)d_in[2];
    const float* pw1_w   = (const float*)d_in[3];
    const float* dw2_w   = (const float*)d_in[4];
    const float* pw2_w   = (const float*)d_in[5];
    const float* dw3_w   = (const float*)d_in[6];
    const float* pw3_w   = (const float*)d_in[7];
    const float* dw4_w   = (const float*)d_in[8];
    const float* pw4_w   = (const float*)d_in[9];
    const float* head_w  = (const float*)d_in[10];
    const float* proj_w  = (const float*)d_in[11];
    const float* proj_b  = (const float*)d_in[12];
    const float* final_w = (const float*)d_in[13];
    const float* final_b = (const float*)d_in[14];

    float *pA,*pB,*den,*bA,*bB,*weff,*sbuf;
    cudaGetSymbolAddress((void**)&pA,  g_pA);
    cudaGetSymbolAddress((void**)&pB,  g_pB);
    cudaGetSymbolAddress((void**)&den, g_den);
    cudaGetSymbolAddress((void**)&bA,  g_bufA);
    cudaGetSymbolAddress((void**)&bB,  g_bufB);
    cudaGetSymbolAddress((void**)&weff,g_weff);
    cudaGetSymbolAddress((void**)&sbuf,g_s);

    cudaFuncSetAttribute(tv5_k<true ,true ,false>, cudaFuncAttributeMaxDynamicSharedMemorySize, TV_SMEM);
    cudaFuncSetAttribute(tv5_k<false,true ,false>, cudaFuncAttributeMaxDynamicSharedMemorySize, TV_SMEM);
    cudaFuncSetAttribute(tv5_k<false,false,true >, cudaFuncAttributeMaxDynamicSharedMemorySize, TV_SMEM);

    dim3 tvg(10,10,BN);
    tv5_k<true ,true ,false><<<tvg,256,TV_SMEM>>>(img, pA, pA, den);  // 1-5   -> pA
    tv5_k<false,true ,false><<<tvg,256,TV_SMEM>>>(img, pA, pB, den);  // 6-10  -> pB
    tv5_k<false,true ,false><<<tvg,256,TV_SMEM>>>(img, pB, pA, den);  // 11-15 -> pA
    tv5_k<false,false,true ><<<tvg,256,TV_SMEM>>>(img, pA, pB, den);  // 16-20 -> den

    stem_k<<<(BN*256*256)/256,256>>>(den, stem_w, bA);                  // [4,32,256,256]
    dw_k<<<(BN*32*128*128)/256,256>>>(bA, dw1_w, bB, 32, 256, 128);     // [4,32,128,128]
    pwb_k<<<dim3(16384/128, 64/64,  BN),128>>>(bB, pw1_w, bA, 64,  32, 16384);
    dw_k<<<(BN*64*64*64)/256,256>>>(bA, dw2_w, bB, 64, 128, 64);
    pwb_k<<<dim3(4096/128, 128/64,  BN),128>>>(bB, pw2_w, bA, 128, 64, 4096);
    dw_k<<<(BN*128*32*32)/256,256>>>(bA, dw3_w, bB, 128, 64, 32);
    pw_k <<<dim3(1024/64, 256/64,   BN),256>>>(bB, pw3_w, bA, 256, 128, 1024);
    dw_k<<<(BN*256*16*16)/256,256>>>(bA, dw4_w, bB, 256, 32, 16);
    pw_k <<<dim3(256/64,  512/64,   BN),256>>>(bB, pw4_w, bA, 512, 256, 256);
    pwb_k<<<dim3(256/128, 1280/64,  BN),128>>>(bA, head_w, bB, 1280, 512, 256);

    weff_k<<<10,256>>>(proj_w, proj_b, final_w, weff, sbuf);
    s_part_k<<<dim3(8,BN),256>>>(bB, weff, sbuf);
    final_k<<<BN*64,256>>>(sbuf, final_b, (float*)d_out);
}